// round 17
// baseline (speedup 1.0000x reference)
#include <cuda_runtime.h>
#include <cuda_bf16.h>
#include <cuda_fp16.h>
#include <cstdint>
#include <math.h>

#define NN 100000
#define EE 3200000
#define NB 98  // ceil(NN/1024)

#define SCAT_BLOCKS ((EE / 2 + 255) / 256)   // 6250  (2 edges per thread)
#define CAST_BLOCKS ((NN * 32 + 255) / 256)  // 12500 (uint4 per thread)

#define ZC_TILES 782   // ceil(NN/128)
#define ZC_CTAX  74    // 74*2*2 = 296 CTAs = one full wave at occ 2
#define O_CTAS   148   // persistent o-GEMM: one CTA per SM at occ 1

// o-GEMM dynamic smem: W fp16 [512][136] = 139264B, then A/epilogue 10240B
#define O_W_BYTES 139264
#define O_SMEM    (O_W_BYTES + 10240)

// ---------------- device scratch (static, no runtime alloc) ----------------
__device__ int   g_is64;
__device__ int   g_deg[NN];
__device__ float g_dis[NN];
__device__ int   g_off[NN + 1];
__device__ int   g_cur[NN];
__device__ int   g_bsum[NB];
__device__ int   g_srcs[EE];                       // CSR-sorted src per dst
__device__ uint4 g_x16   [(size_t)NN * 32];        // fp16 dis-scaled [latent|cond]
__device__ uint4 g_xagg16[(size_t)NN * 32];        // fp16 aggregated features (256)
__device__ uint4 g_act16 [(size_t)NN * 64];        // fp16 tanh activations (512)
__device__ uint2 g_h16   [(size_t)NN * 32];        // fp16 dis-scaled h2 (128)

// ==================== warp-MMA helpers (sm_80+ HMMA path) ====================
__device__ __forceinline__ uint32_t smem_u32(const void* p) {
    uint32_t a;
    asm("{ .reg .u64 t; cvta.to.shared.u64 t, %1; cvt.u32.u64 %0, t; }" : "=r"(a) : "l"(p));
    return a;
}

// fp16 x fp16 -> fp32 accumulate
__device__ __forceinline__ void mma16816h(float* d, const uint32_t* a, const uint32_t* b) {
    asm volatile(
        "mma.sync.aligned.m16n8k16.row.col.f32.f16.f16.f32 "
        "{%0,%1,%2,%3}, {%4,%5,%6,%7}, {%8,%9}, {%0,%1,%2,%3};"
        : "+f"(d[0]), "+f"(d[1]), "+f"(d[2]), "+f"(d[3])
        : "r"(a[0]), "r"(a[1]), "r"(a[2]), "r"(a[3]), "r"(b[0]), "r"(b[1]));
}

__device__ __forceinline__ void ldmx4(uint32_t* r, uint32_t addr) {
    asm volatile("ldmatrix.sync.aligned.m8n8.x4.shared.b16 {%0,%1,%2,%3}, [%4];"
                 : "=r"(r[0]), "=r"(r[1]), "=r"(r[2]), "=r"(r[3]) : "r"(addr));
}
__device__ __forceinline__ void ldmx4t(uint32_t* r, uint32_t addr) {
    asm volatile("ldmatrix.sync.aligned.m8n8.x4.trans.shared.b16 {%0,%1,%2,%3}, [%4];"
                 : "=r"(r[0]), "=r"(r[1]), "=r"(r[2]), "=r"(r[3]) : "r"(addr));
}

// pack fp32x4 -> fp16x4 (round-to-nearest)
__device__ __forceinline__ uint2 pack4h(float4 v) {
    uint2 u;
    __half2 a = __floats2half2_rn(v.x, v.y);
    __half2 b = __floats2half2_rn(v.z, v.w);
    u.x = *(uint32_t*)&a;
    u.y = *(uint32_t*)&b;
    return u;
}

// ==================== persistent zc GEMM: W resident in smem ====================
// Grid (74, 2, 2); each CTA: convert its 128x128 fp32 W slice to fp16 smem ONCE,
// then loop row tiles with stride. A single-buffered, register-prefetched.
// smem: [0, 34816) W fp16 [128][136]; [34816, 45056) A [128][40] / epi patches.
__global__ void __launch_bounds__(256, 2) gemm_zc_mma(const float* __restrict__ Wz,
                                                      const float* __restrict__ bz,
                                                      const float* __restrict__ Wc,
                                                      const float* __restrict__ bc) {
    __shared__ __align__(16) char smemblk[45056];
    int conv = blockIdx.z;
    int nb = blockIdx.y * 128;
    const float* W = conv ? Wc : Wz;
    const float* bias = (conv ? bc : bz) + nb;
    const __half* A = (const __half*)g_xagg16 + conv * 128;
    __half* C = (__half*)g_act16 + conv * 256 + nb;

    int tid = threadIdx.x, lane = tid & 31, wid = tid >> 5;
    int wm = wid & 3, wn = wid >> 2;  // warp tile: rows [wm*32,+32), cols [wn*64,+64)

    // ---- stage W fp32 -> fp16 resident (128 rows x 128 cols, stride 136 halves)
    #pragma unroll
    for (int i = 0; i < 16; i++) {
        int lin = tid + 256 * i;   // 0..4095 float4 slots
        int kr = lin >> 5;         // K row 0..127
        int c4 = lin & 31;         // float4 column
        float4 v = *(const float4*)(W + (size_t)kr * 256 + nb + c4 * 4);
        *(uint2*)(smemblk + (kr * 136 + c4 * 4) * 2) = pack4h(v);
    }

    uint32_t base = smem_u32(smemblk);
    uint32_t aW = base;
    uint32_t aA = base + 34816;
    uint32_t offA0 = (uint32_t)(((wm * 32 + (lane & 15)) * 40 + ((lane >> 4) << 3)) * 2);
    uint32_t offB0 = (uint32_t)(((lane & 15) * 136 + wn * 64 + ((lane >> 4) << 3)) * 2);

    int ar0 = tid >> 2,         ac0 = (tid & 3) * 8;
    int ar1 = (tid + 256) >> 2, ac1 = ((tid + 256) & 3) * 8;

    for (int tile = blockIdx.x; tile < ZC_TILES; tile += ZC_CTAX) {
        int row0 = tile * 128;
        float acc[2][8][4];
        #pragma unroll
        for (int i = 0; i < 2; i++)
            #pragma unroll
            for (int j = 0; j < 8; j++)
                #pragma unroll
                for (int k = 0; k < 4; k++) acc[i][j][k] = 0.f;

        uint4 areg[2];
        {
            int g0 = row0 + ar0, g1 = row0 + ar1;
            areg[0] = (g0 < NN) ? *(const uint4*)(A + (size_t)g0 * 256 + ac0)
                                : make_uint4(0u, 0u, 0u, 0u);
            areg[1] = (g1 < NN) ? *(const uint4*)(A + (size_t)g1 * 256 + ac1)
                                : make_uint4(0u, 0u, 0u, 0u);
        }
        #pragma unroll
        for (int ch = 0; ch < 4; ch++) {
            __syncthreads();  // prior smem reads done
            *(uint4*)(smemblk + 34816 + (ar0 * 40 + ac0) * 2) = areg[0];
            *(uint4*)(smemblk + 34816 + (ar1 * 40 + ac1) * 2) = areg[1];
            __syncthreads();  // A chunk visible
            if (ch < 3) {
                int g0 = row0 + ar0, g1 = row0 + ar1;
                int kofs = (ch + 1) * 32;
                areg[0] = (g0 < NN) ? *(const uint4*)(A + (size_t)g0 * 256 + kofs + ac0)
                                    : make_uint4(0u, 0u, 0u, 0u);
                areg[1] = (g1 < NN) ? *(const uint4*)(A + (size_t)g1 * 256 + kofs + ac1)
                                    : make_uint4(0u, 0u, 0u, 0u);
            }
            #pragma unroll
            for (int kb = 0; kb < 32; kb += 16) {
                uint32_t a[2][4], bb[4][4];
                #pragma unroll
                for (int mi = 0; mi < 2; mi++)
                    ldmx4(a[mi], aA + offA0 + (uint32_t)((mi * 16 * 40 + kb) * 2));
                #pragma unroll
                for (int g = 0; g < 4; g++)
                    ldmx4t(bb[g], aW + offB0 +
                           (uint32_t)(((ch * 32 + kb) * 136 + g * 16) * 2));
                #pragma unroll
                for (int mi = 0; mi < 2; mi++)
                    #pragma unroll
                    for (int g = 0; g < 4; g++) {
                        mma16816h(acc[mi][2 * g],     a[mi], &bb[g][0]);
                        mma16816h(acc[mi][2 * g + 1], a[mi], &bb[g][2]);
                    }
            }
        }
        __syncthreads();  // MMA reads of A region done -> reuse as epilogue patches

        char* patch = smemblk + 34816 + wid * 1152;  // 8 rows x 72 halves
        #pragma unroll
        for (int qp = 0; qp < 4; qp++) {
            int mi = qp >> 1, h = qp & 1;
            int lr = lane >> 2;
            #pragma unroll
            for (int ni = 0; ni < 8; ni++) {
                int lc = ni * 8 + (lane & 3) * 2;
                float v0 = acc[mi][ni][2 * h]     + bias[wn * 64 + lc];
                float v1 = acc[mi][ni][2 * h + 1] + bias[wn * 64 + lc + 1];
                v0 = tanhf(v0);
                v1 = tanhf(v1);
                *(__half2*)(patch + (lr * 72 + lc) * 2) = __floats2half2_rn(v0, v1);
            }
            __syncwarp();
            #pragma unroll
            for (int it = 0; it < 2; it++) {
                int lr2 = it * 4 + (lane >> 3);
                int seg = lane & 7;
                int gr = row0 + wm * 32 + qp * 8 + lr2;
                uint4 v = *(uint4*)(patch + (lr2 * 72 + seg * 8) * 2);
                if (gr < NN)
                    *(uint4*)(C + (size_t)gr * 512 + wn * 64 + seg * 8) = v;
            }
            __syncwarp();
        }
    }
}

// ==================== persistent o GEMM: full Wo resident in dynamic smem ============
// Grid 148, occ 1 (149.5KB dyn smem). Each CTA converts Wo (512x128 fp32) to fp16
// smem ONCE (same pack4h rounding), then loops ~5.3 row tiles. Output: g_h16 = dis*D.
__global__ void __launch_bounds__(256, 1) gemm_o_mma(const float* __restrict__ Wo) {
    extern __shared__ __align__(16) char smemblk[];
    const __half* A = (const __half*)g_act16;
    __half* C = (__half*)g_h16;

    int tid = threadIdx.x, lane = tid & 31, wid = tid >> 5;
    int wm = wid & 3, wn = wid >> 2;  // wn in 0..1 (N=128)

    // ---- stage Wo fp32 -> fp16 resident (512 rows x 128 cols, stride 136 halves)
    #pragma unroll
    for (int i = 0; i < 64; i++) {
        int lin = tid + 256 * i;   // 0..16383 float4 slots
        int kr = lin >> 5;         // K row 0..511
        int c4 = lin & 31;         // float4 column 0..31
        float4 v = *(const float4*)(Wo + (size_t)kr * 128 + c4 * 4);
        *(uint2*)(smemblk + (kr * 136 + c4 * 4) * 2) = pack4h(v);
    }

    uint32_t base = smem_u32(smemblk);
    uint32_t aW = base;
    uint32_t aA = base + O_W_BYTES;
    uint32_t offA0 = (uint32_t)(((wm * 32 + (lane & 15)) * 40 + ((lane >> 4) << 3)) * 2);
    uint32_t offB0 = (uint32_t)(((lane & 15) * 136 + wn * 64 + ((lane >> 4) << 3)) * 2);

    int ar0 = tid >> 2,         ac0 = (tid & 3) * 8;
    int ar1 = (tid + 256) >> 2, ac1 = ((tid + 256) & 3) * 8;

    for (int tile = blockIdx.x; tile < ZC_TILES; tile += O_CTAS) {
        int row0 = tile * 128;
        float acc[2][8][4];
        #pragma unroll
        for (int i = 0; i < 2; i++)
            #pragma unroll
            for (int j = 0; j < 8; j++)
                #pragma unroll
                for (int k = 0; k < 4; k++) acc[i][j][k] = 0.f;

        uint4 areg[2];
        {
            int g0 = row0 + ar0, g1 = row0 + ar1;
            areg[0] = (g0 < NN) ? *(const uint4*)(A + (size_t)g0 * 512 + ac0)
                                : make_uint4(0u, 0u, 0u, 0u);
            areg[1] = (g1 < NN) ? *(const uint4*)(A + (size_t)g1 * 512 + ac1)
                                : make_uint4(0u, 0u, 0u, 0u);
        }
        for (int ch = 0; ch < 16; ch++) {
            __syncthreads();  // prior smem reads done (W stores on 1st iteration)
            *(uint4*)(smemblk + O_W_BYTES + (ar0 * 40 + ac0) * 2) = areg[0];
            *(uint4*)(smemblk + O_W_BYTES + (ar1 * 40 + ac1) * 2) = areg[1];
            __syncthreads();  // A chunk visible
            if (ch < 15) {    // prefetch next chunk during MMAs
                int g0 = row0 + ar0, g1 = row0 + ar1;
                int kofs = (ch + 1) * 32;
                areg[0] = (g0 < NN) ? *(const uint4*)(A + (size_t)g0 * 512 + kofs + ac0)
                                    : make_uint4(0u, 0u, 0u, 0u);
                areg[1] = (g1 < NN) ? *(const uint4*)(A + (size_t)g1 * 512 + kofs + ac1)
                                    : make_uint4(0u, 0u, 0u, 0u);
            }
            #pragma unroll
            for (int kb = 0; kb < 32; kb += 16) {
                uint32_t a[2][4], bb[4][4];
                #pragma unroll
                for (int mi = 0; mi < 2; mi++)
                    ldmx4(a[mi], aA + offA0 + (uint32_t)((mi * 16 * 40 + kb) * 2));
                #pragma unroll
                for (int g = 0; g < 4; g++)
                    ldmx4t(bb[g], aW + offB0 +
                           (uint32_t)(((ch * 32 + kb) * 136 + g * 16) * 2));
                #pragma unroll
                for (int mi = 0; mi < 2; mi++)
                    #pragma unroll
                    for (int g = 0; g < 4; g++) {
                        mma16816h(acc[mi][2 * g],     a[mi], &bb[g][0]);
                        mma16816h(acc[mi][2 * g + 1], a[mi], &bb[g][2]);
                    }
            }
        }
        __syncthreads();  // MMA reads of A region done -> reuse as epilogue patches

        char* patch = smemblk + O_W_BYTES + wid * 1152;  // 8 rows x 72 halves
        #pragma unroll
        for (int qp = 0; qp < 4; qp++) {
            int mi = qp >> 1, h = qp & 1;
            int lr = lane >> 2;
            int gr0 = row0 + wm * 32 + qp * 8 + lr;
            float dd = (gr0 < NN) ? g_dis[gr0] : 0.f;
            #pragma unroll
            for (int ni = 0; ni < 8; ni++) {
                int lc = ni * 8 + (lane & 3) * 2;
                float v0 = dd * acc[mi][ni][2 * h];
                float v1 = dd * acc[mi][ni][2 * h + 1];
                *(__half2*)(patch + (lr * 72 + lc) * 2) = __floats2half2_rn(v0, v1);
            }
            __syncwarp();
            #pragma unroll
            for (int it = 0; it < 2; it++) {
                int lr2 = it * 4 + (lane >> 3);
                int seg = lane & 7;
                int gr = row0 + wm * 32 + qp * 8 + lr2;
                uint4 v = *(uint4*)(patch + (lr2 * 72 + seg * 8) * 2);
                if (gr < NN)
                    *(uint4*)(C + (size_t)gr * 128 + wn * 64 + seg * 8) = v;
            }
            __syncwarp();
        }
    }
}

// ---------------- fused dtype detect + degree init ----------------
__global__ void detect_init_kernel(const unsigned int* __restrict__ w) {
    int i = blockIdx.x * blockDim.x + threadIdx.x;
    if (i < NN) g_deg[i] = 1;  // self loop pre-counted
    if (blockIdx.x == 0) {
        // If int64 (LE), high word of every value (<100000) is 0; sample 2048.
        int bad = 0;
        for (int k = threadIdx.x; k < 2048; k += blockDim.x)
            if (w[2 * k + 1] != 0u) bad = 1;
        if (__syncthreads_or(bad)) {
            if (threadIdx.x == 0) g_is64 = 0;
        } else {
            if (threadIdx.x == 0) g_is64 = 1;
        }
    }
}

// ---------------- degree count (4 edges/thread, vectorized decode) -----------
__global__ void count_kernel(const void* __restrict__ ei) {
    int e4 = blockIdx.x * blockDim.x + threadIdx.x;  // quad index
    if (e4 >= EE / 4) return;
    int d0, d1, d2, d3;
    if (g_is64) {
        const longlong2* pd = (const longlong2*)((const long long*)ei + EE);
        longlong2 v0 = pd[2 * e4];
        longlong2 v1 = pd[2 * e4 + 1];
        d0 = (int)v0.x; d1 = (int)v0.y; d2 = (int)v1.x; d3 = (int)v1.y;
    } else {
        const int4* pd = (const int4*)((const int*)ei + EE);
        int4 v = pd[e4];
        d0 = v.x; d1 = v.y; d2 = v.z; d3 = v.w;
    }
    atomicAdd(&g_deg[d0], 1);
    atomicAdd(&g_deg[d1], 1);
    atomicAdd(&g_deg[d2], 1);
    atomicAdd(&g_deg[d3], 1);
}

__global__ void scan1_kernel() {
    __shared__ int sh[1024];
    int i = blockIdx.x * 1024 + threadIdx.x;
    int v = 0;
    if (i < NN) {
        int d = g_deg[i];
        g_dis[i] = rsqrtf((float)d);
        v = d - 1;
    }
    sh[threadIdx.x] = v;
    __syncthreads();
    for (int ofs = 1; ofs < 1024; ofs <<= 1) {
        int t = 0;
        if ((int)threadIdx.x >= ofs) t = sh[threadIdx.x - ofs];
        __syncthreads();
        sh[threadIdx.x] += t;
        __syncthreads();
    }
    int incl = sh[threadIdx.x];
    if (i < NN) g_off[i] = incl - v;  // exclusive within block
    if (threadIdx.x == 1023) g_bsum[blockIdx.x] = incl;
}

// scan3 with scan2 folded in: every block redundantly scans the 98 block sums.
__global__ void scan3_kernel() {
    __shared__ int sh[128];
    int t = threadIdx.x;
    if (t < 128) {
        int v = (t < NB) ? g_bsum[t] : 0;
        sh[t] = v;
        __syncthreads();
        for (int ofs = 1; ofs < 128; ofs <<= 1) {
            int u = (t >= ofs) ? sh[t - ofs] : 0;
            __syncthreads();
            sh[t] += u;
            __syncthreads();
        }
        if (t < 128) sh[t] -= v;  // exclusive
    } else {
        for (int ofs = 1; ofs < 128; ofs <<= 1) { __syncthreads(); __syncthreads(); }
    }
    __syncthreads();
    int base = sh[blockIdx.x];
    int i = blockIdx.x * 1024 + t;
    if (i < NN) {
        int o = g_off[i] + base;
        g_off[i] = o;
        g_cur[i] = o;
    }
    if (i == 0) g_off[NN] = EE;
}

// ---------------- fused scatter (CSR fill, 2 edges/thread) + cast (uint4/thread)
__global__ void __launch_bounds__(256) scatter_cast_kernel(
        const void* __restrict__ ei,
        const float* __restrict__ lat, const float* __restrict__ cond) {
    int b = blockIdx.x;
    if (b < SCAT_BLOCKS) {
        int e2 = b * 256 + threadIdx.x;  // pair index
        if (e2 >= EE / 2) return;
        int s0, s1, d0, d1;
        if (g_is64) {
            const longlong2* ps = (const longlong2*)ei;
            const longlong2* pd = (const longlong2*)((const long long*)ei + EE);
            longlong2 sv = ps[e2];
            longlong2 dv = pd[e2];
            s0 = (int)sv.x; s1 = (int)sv.y;
            d0 = (int)dv.x; d1 = (int)dv.y;
        } else {
            const int2* ps = (const int2*)ei;
            const int2* pd = (const int2*)((const int*)ei + EE);
            int2 sv = ps[e2];
            int2 dv = pd[e2];
            s0 = sv.x; s1 = sv.y;
            d0 = dv.x; d1 = dv.y;
        }
        g_srcs[atomicAdd(&g_cur[d0], 1)] = s0;
        g_srcs[atomicAdd(&g_cur[d1], 1)] = s1;
    } else {
        int t = (b - SCAT_BLOCKS) * 256 + threadIdx.x;  // over NN*32 uint4 slots
        if (t >= NN * 32) return;
        int node = t >> 5;
        int c8 = t & 31;   // which 8-half group of the 256-wide row
        float dd = g_dis[node];
        const float4* src = (c8 < 16)
            ? ((const float4*)lat  + (size_t)node * 32 + 2 * c8)
            : ((const float4*)cond + (size_t)node * 32 + 2 * (c8 - 16));
        float4 v0 = src[0];
        float4 v1 = src[1];
        uint4 o;
        __half2* oh = (__half2*)&o;
        oh[0] = __floats2half2_rn(dd * v0.x, dd * v0.y);
        oh[1] = __floats2half2_rn(dd * v0.z, dd * v0.w);
        oh[2] = __floats2half2_rn(dd * v1.x, dd * v1.y);
        oh[3] = __floats2half2_rn(dd * v1.z, dd * v1.w);
        g_x16[(size_t)node * 32 + c8] = o;
    }
}

// ---------------- unpack-accumulate helpers ----------------
__device__ __forceinline__ void acc8(float* a, uint4 v) {
    const __half2* h = (const __half2*)&v;
    #pragma unroll
    for (int k = 0; k < 4; k++) {
        float2 f = __half22float2(h[k]);
        a[2 * k] += f.x;
        a[2 * k + 1] += f.y;
    }
}
__device__ __forceinline__ void acc4(float* a, uint2 v) {
    const __half2* h = (const __half2*)&v;
    float2 f0 = __half22float2(h[0]);
    float2 f1 = __half22float2(h[1]);
    a[0] += f0.x; a[1] += f0.y; a[2] += f1.x; a[3] += f1.y;
}

// ---------------- aggregation 1: fp16 gather, 512B/node, warp-per-node -----
__global__ void __launch_bounds__(256) aggx_kernel() {
    int gw = (int)((blockIdx.x * blockDim.x + threadIdx.x) >> 5);
    int lane = threadIdx.x & 31;
    if (gw >= NN) return;
    float dd = g_dis[gw];
    float a[8];
    #pragma unroll
    for (int k = 0; k < 8; k++) a[k] = 0.f;
    acc8(a, g_x16[(size_t)gw * 32 + lane]);  // self term (pre-scaled by dis)
    int beg = g_off[gw], end = g_off[gw + 1];
    #pragma unroll 8
    for (int j = beg; j < end; ++j) {
        int s = g_srcs[j];
        acc8(a, g_x16[(size_t)s * 32 + lane]);
    }
    uint4 o;
    __half2* oh = (__half2*)&o;
    #pragma unroll
    for (int k = 0; k < 4; k++)
        oh[k] = __floats2half2_rn(dd * a[2 * k], dd * a[2 * k + 1]);
    g_xagg16[(size_t)gw * 32 + lane] = o;
}

// ---------------- aggregation 2: fp16 gather, 256B/node, warp-per-node -----
__global__ void __launch_bounds__(256) agg2_kernel(const float* __restrict__ bo,
                                                   float* __restrict__ out) {
    int gw = (int)((blockIdx.x * blockDim.x + threadIdx.x) >> 5);
    int lane = threadIdx.x & 31;
    if (gw >= NN) return;
    float dd = g_dis[gw];
    float a[4];
    #pragma unroll
    for (int k = 0; k < 4; k++) a[k] = 0.f;
    acc4(a, g_h16[(size_t)gw * 32 + lane]);  // self term
    int beg = g_off[gw], end = g_off[gw + 1];
    #pragma unroll 8
    for (int j = beg; j < end; ++j) {
        int s = g_srcs[j];
        acc4(a, g_h16[(size_t)s * 32 + lane]);
    }
    float4 b = ((const float4*)bo)[lane];
    ((float4*)out)[(size_t)gw * 32 + lane] =
        make_float4(dd * a[0] + b.x, dd * a[1] + b.y, dd * a[2] + b.z, dd * a[3] + b.w);
}

// ---------------- launch ----------------
extern "C" void kernel_launch(void* const* d_in, const int* in_sizes, int n_in,
                              void* d_out, int out_size) {
    const float* latent    = (const float*)d_in[0];
    const float* condition = (const float*)d_in[1];
    const void*  ei        = d_in[2];
    const float* Wz = (const float*)d_in[3];
    const float* bz = (const float*)d_in[4];
    const float* Wc = (const float*)d_in[5];
    const float* bc = (const float*)d_in[6];
    const float* Wo = (const float*)d_in[7];
    const float* bo = (const float*)d_in[8];
    float* out = (float*)d_out;

    static int smem_set = 0;
    if (!smem_set) {
        cudaFuncSetAttribute(gemm_o_mma, cudaFuncAttributeMaxDynamicSharedMemorySize,
                             O_SMEM);
        smem_set = 1;
    }

    detect_init_kernel<<<(NN + 255) / 256, 256>>>((const unsigned int*)ei);
    count_kernel<<<(EE / 4 + 255) / 256, 256>>>(ei);
    scan1_kernel<<<NB, 1024>>>();
    scan3_kernel<<<NB, 1024>>>();
    scatter_cast_kernel<<<SCAT_BLOCKS + CAST_BLOCKS, 256>>>(ei, latent, condition);
    aggx_kernel<<<(NN * 32 + 255) / 256, 256>>>();

    gemm_zc_mma<<<dim3(ZC_CTAX, 2, 2), 256>>>(Wz, bz, Wc, bc);
    gemm_o_mma<<<O_CTAS, 256, O_SMEM>>>(Wo);

    agg2_kernel<<<(NN * 32 + 255) / 256, 256>>>(bo, out);
}